// round 15
// baseline (speedup 1.0000x reference)
#include <cuda_runtime.h>
#include <cuda_fp16.h>
#include <math.h>

// Problem constants
#define Bb 2
#define Tt 2048
#define Ee 2048
#define BT (Bb*Tt)          // 4096
#define Hh 16
#define HKV 4
#define MM 4
#define HD 32
#define EKV 512
#define HALF 16             // HD/2
// q is pre-scaled by SCALEF*log2(e) in the q-projection epilogue,
// so scores feed exp2f directly.
#define QSCALE 0.25503485202f

// -------- scratch buffers (no cudaMalloc allowed) --------
__device__ __align__(128) unsigned g_qh[(size_t)BT * Ee / 2];   // q rope fp16 hi (pre-scaled)
__device__ __align__(128) unsigned g_ql[(size_t)BT * Ee / 2];   // q rope fp16 lo
__device__ __align__(128) unsigned g_kh[(size_t)BT * EKV / 2];  // k rope fp16
__device__ __align__(128) unsigned g_vh[(size_t)BT * EKV / 2];  // v fp16
__device__ __align__(128) float    g_L [(size_t)Bb * Hh * MM * Tt];
__device__ __align__(128) unsigned g_nh[(size_t)BT * Ee / 2];   // combined+rmsnorm fp16
// fp16-packed GEMM operands
__device__ __align__(128) unsigned g_xh [(size_t)BT * Ee / 2];
__device__ __align__(128) unsigned g_qwh[(size_t)Ee * Ee / 2];
__device__ __align__(128) unsigned g_kwh[(size_t)EKV * Ee / 2];
__device__ __align__(128) unsigned g_vwh[(size_t)EKV * Ee / 2];
__device__ __align__(128) unsigned g_owh[(size_t)Ee * Ee / 2];

// ------------------------------------------------------------
// helpers
// ------------------------------------------------------------
__device__ __forceinline__ void mma_f16(float c[4], const unsigned a[4], const unsigned b[2])
{
    asm volatile(
        "mma.sync.aligned.m16n8k16.row.col.f32.f16.f16.f32 "
        "{%0,%1,%2,%3}, {%4,%5,%6,%7}, {%8,%9}, {%0,%1,%2,%3};\n"
        : "+f"(c[0]), "+f"(c[1]), "+f"(c[2]), "+f"(c[3])
        : "r"(a[0]), "r"(a[1]), "r"(a[2]), "r"(a[3]), "r"(b[0]), "r"(b[1]));
}
__device__ __forceinline__ void ldsm4(unsigned r[4], const unsigned* p)
{
    unsigned a = (unsigned)__cvta_generic_to_shared(p);
    asm volatile("ldmatrix.sync.aligned.m8n8.x4.shared.b16 {%0,%1,%2,%3}, [%4];"
        : "=r"(r[0]), "=r"(r[1]), "=r"(r[2]), "=r"(r[3]) : "r"(a));
}
__device__ __forceinline__ void ldsm4t(unsigned r[4], const unsigned* p)
{
    unsigned a = (unsigned)__cvta_generic_to_shared(p);
    asm volatile("ldmatrix.sync.aligned.m8n8.x4.trans.shared.b16 {%0,%1,%2,%3}, [%4];"
        : "=r"(r[0]), "=r"(r[1]), "=r"(r[2]), "=r"(r[3]) : "r"(a));
}
__device__ __forceinline__ unsigned pack_f16(float lo, float hi)
{
    unsigned d;
    asm("cvt.rn.f16x2.f32 %0, %1, %2;\n" : "=r"(d) : "f"(hi), "f"(lo));
    return d;
}
__device__ __forceinline__ float2 unpack_f16(unsigned u)
{
    __half2 h = *reinterpret_cast<__half2*>(&u);
    return __half22float2(h);   // x = lo, y = hi
}
__device__ __forceinline__ void split_pair_f16(float v0, float v1, unsigned& hi, unsigned& lo)
{
    hi = pack_f16(v0, v1);
    float2 hf = unpack_f16(hi);
    lo = pack_f16(v0 - hf.x, v1 - hf.y);
}

#define CP_COMMIT() asm volatile("cp.async.commit_group;\n")
#define CP_WAIT0()  asm volatile("cp.async.wait_group 0;\n")
#define CP_WAIT1()  asm volatile("cp.async.wait_group 1;\n")
__device__ __forceinline__ void cp16(unsigned dst, const unsigned* src)
{
    asm volatile("cp.async.cg.shared.global [%0], [%1], 16;\n" :: "r"(dst), "l"(src));
}

// ------------------------------------------------------------
// f32 -> packed fp16 convert
// ------------------------------------------------------------
__global__ __launch_bounds__(256)
void cvt_f16(const float* __restrict__ s, unsigned* __restrict__ d)
{
    size_t i = ((size_t)blockIdx.x * 256 + threadIdx.x) * 4;
    float4 v = *(const float4*)(s + i);
    *(uint2*)(d + (i >> 1)) = make_uint2(pack_f16(v.x, v.y), pack_f16(v.z, v.w));
}

// ============================================================
// fp16 tensor-core GEMM: C[m,n] = sum_k A[m,k]*W[n,k]
// MODE 0: f32 out. MODE 2: RoPE + QSCALE + fp16 hi/lo out.
// MODE 4: fp16 out. MODE 5: RoPE + fp16 out.
// ============================================================
#define G4STR 36
#define G4_STAGE (128 * G4STR)
#define G4_SMEM_BYTES (4 * G4_STAGE * 4)

__device__ __forceinline__ void g4_issue(
    const unsigned* __restrict__ A, const unsigned* __restrict__ W,
    int Kw, int m0, int n0, int kw0,
    unsigned* __restrict__ asb, unsigned* __restrict__ bsb, int tid)
{
#pragma unroll
    for (int i = 0; i < 4; ++i) {
        int idx = tid + i * 256;
        int row = idx >> 3;
        int ch  = idx & 7;
        unsigned sA = (unsigned)__cvta_generic_to_shared(asb + row * G4STR + ch * 4);
        cp16(sA, A + (size_t)(m0 + row) * Kw + kw0 + ch * 4);
        unsigned sB = (unsigned)__cvta_generic_to_shared(bsb + row * G4STR + ch * 4);
        cp16(sB, W + (size_t)(n0 + row) * Kw + kw0 + ch * 4);
    }
    CP_COMMIT();
}

template<int MODE>
__global__ __launch_bounds__(256, 2)
void gemm_f16_v4(const unsigned* __restrict__ A, const unsigned* __restrict__ W,
                 float* __restrict__ C, unsigned* __restrict__ Chi,
                 unsigned* __restrict__ Clo, int N, int K,
                 const float* __restrict__ cosp, const float* __restrict__ sinp)
{
    extern __shared__ unsigned g4sm[];
    unsigned* As0 = g4sm;
    unsigned* As1 = g4sm + G4_STAGE;
    unsigned* Bs0 = g4sm + 2 * G4_STAGE;
    unsigned* Bs1 = g4sm + 3 * G4_STAGE;

    const int tid  = threadIdx.x;
    const int lane = tid & 31;
    const int warp = tid >> 5;
    const int g    = lane >> 2;
    const int tig  = lane & 3;
    const int wm   = warp >> 1;
    const int wn   = warp & 1;
    const int m0 = blockIdx.y * 128;
    const int n0 = blockIdx.x * 128;
    const int Kw = K / 2;

    const int a_row = lane & 15;
    const int a_c   = (lane >> 4) << 2;
    const int b_row = (lane & 7) + ((lane >> 4) << 3);
    const int b_c   = ((lane >> 3) & 1) << 2;

    float c[2][8][4];
#pragma unroll
    for (int mt = 0; mt < 2; ++mt)
#pragma unroll
        for (int nt = 0; nt < 8; ++nt)
#pragma unroll
            for (int r = 0; r < 4; ++r) c[mt][nt][r] = 0.f;

    g4_issue(A, W, Kw, m0, n0, 0, As0, Bs0, tid);

    const int NT = K / 64;
    for (int kt = 0; kt < NT; ++kt) {
        if (kt + 1 < NT) {
            g4_issue(A, W, Kw, m0, n0, (kt + 1) * 32,
                     ((kt + 1) & 1) ? As1 : As0, ((kt + 1) & 1) ? Bs1 : Bs0, tid);
            CP_WAIT1();
        } else {
            CP_WAIT0();
        }
        __syncthreads();

        const unsigned* ab = ((kt & 1) ? As1 : As0) + (wm * 32) * G4STR;
        const unsigned* bb = ((kt & 1) ? Bs1 : Bs0) + (wn * 64) * G4STR;

#pragma unroll
        for (int kc = 0; kc < 4; ++kc) {
            const int k0w = kc * 8;
            unsigned a[2][4], b[8][2];
#pragma unroll
            for (int mt = 0; mt < 2; ++mt)
                ldsm4(a[mt], ab + (mt * 16 + a_row) * G4STR + k0w + a_c);
#pragma unroll
            for (int u = 0; u < 4; ++u) {
                unsigned r[4];
                ldsm4(r, bb + (u * 16 + b_row) * G4STR + k0w + b_c);
                b[2 * u][0]     = r[0];
                b[2 * u][1]     = r[1];
                b[2 * u + 1][0] = r[2];
                b[2 * u + 1][1] = r[3];
            }
#pragma unroll
            for (int mt = 0; mt < 2; ++mt)
#pragma unroll
                for (int nt = 0; nt < 8; ++nt)
                    mma_f16(c[mt][nt], a[mt], b[nt]);
        }
        __syncthreads();
    }

#pragma unroll
    for (int mt = 0; mt < 2; ++mt) {
        int mA = m0 + wm * 32 + mt * 16 + g;
        int mB = mA + 8;
#pragma unroll
        for (int nt = 0; nt < 8; ++nt) {
            int n = n0 + wn * 64 + nt * 8 + tig * 2;
            float v0 = c[mt][nt][0], v1 = c[mt][nt][1];
            float v2 = c[mt][nt][2], v3 = c[mt][nt][3];
            if (MODE == 2 || MODE == 5) {
                int p = (n & 31) >> 1;
                int tA = mA & (Tt - 1), tB = mB & (Tt - 1);
                float cA = cosp[tA * HALF + p], snA = sinp[tA * HALF + p];
                float cB = cosp[tB * HALF + p], snB = sinp[tB * HALF + p];
                float e = v0, o = v1;
                v0 = e * cA - o * snA; v1 = e * snA + o * cA;
                e = v2; o = v3;
                v2 = e * cB - o * snB; v3 = e * snB + o * cB;
            }
            if (MODE == 2) {
                v0 *= QSCALE; v1 *= QSCALE; v2 *= QSCALE; v3 *= QSCALE;
                unsigned hi, lo;
                split_pair_f16(v0, v1, hi, lo);
                size_t wA = ((size_t)mA * N + n) >> 1;
                Chi[wA] = hi; Clo[wA] = lo;
                split_pair_f16(v2, v3, hi, lo);
                size_t wB = ((size_t)mB * N + n) >> 1;
                Chi[wB] = hi; Clo[wB] = lo;
            } else if (MODE == 4 || MODE == 5) {
                Chi[((size_t)mA * N + n) >> 1] = pack_f16(v0, v1);
                Chi[((size_t)mB * N + n) >> 1] = pack_f16(v2, v3);
            } else {
                *(float2*)(C + (size_t)mA * N + n) = make_float2(v0, v1);
                *(float2*)(C + (size_t)mB * N + n) = make_float2(v2, v3);
            }
        }
    }
}

// ============================================================
// split-fp16 attention, 2-pass. Scores come out exp2-ready.
// pass1: 1-term QK -> denominators only, 3 CTA/SM.
// pass2: 2-term QK + 2-term PV, software-pipelined member loop
//        (member i+1's mma issued before member i's exp phase).
// ============================================================
#define STR68 68

template<int ROWS>
__device__ __forceinline__ void copy_tile_async(const unsigned* __restrict__ gsrc, int grs,
                                                unsigned* __restrict__ dst, int tid)
{
#pragma unroll
    for (int it = 0; it < ROWS / 16; ++it) {
        int idx = tid + it * 256;
        int row = idx >> 4;
        int c4  = (idx & 15) << 2;
        unsigned s = (unsigned)__cvta_generic_to_shared(dst + row * STR68 + c4);
        const unsigned* gp = gsrc + (size_t)row * grs + c4;
        asm volatile("cp.async.cg.shared.global [%0], [%1], 16;\n" :: "r"(s), "l"(gp));
    }
}

__device__ __forceinline__ void qk_member_f16(
    const unsigned* __restrict__ qh, const unsigned* __restrict__ ql,
    const unsigned* __restrict__ kh,
    int qrow0, int lane, int i, float sc[8][4])
{
    const int ar = qrow0 + (lane & 15);
    const int ac = (lane >> 4) << 2;
    const int kr = (lane & 7) + ((lane >> 4) << 3);
    const int kc = ((lane >> 3) & 1) << 2;
#pragma unroll
    for (int c = 0; c < 2; ++c) {
        const int k0w = i * 16 + c * 8;
        unsigned ah[4], al[4];
        ldsm4(ah, qh + ar * STR68 + k0w + ac);
        ldsm4(al, ql + ar * STR68 + k0w + ac);
#pragma unroll
        for (int u = 0; u < 4; ++u) {
            unsigned bh[4];
            ldsm4(bh, kh + (16 * u + kr) * STR68 + k0w + kc);
            mma_f16(sc[2 * u],     ah, bh);
            mma_f16(sc[2 * u + 1], ah, bh + 2);
            mma_f16(sc[2 * u],     al, bh);
            mma_f16(sc[2 * u + 1], al, bh + 2);
        }
    }
}

__device__ __forceinline__ void qk_member_f16_1t(
    const unsigned* __restrict__ qh, const unsigned* __restrict__ kh,
    int qrow0, int lane, int i, float sc[8][4])
{
    const int ar = qrow0 + (lane & 15);
    const int ac = (lane >> 4) << 2;
    const int kr = (lane & 7) + ((lane >> 4) << 3);
    const int kc = ((lane >> 3) & 1) << 2;
#pragma unroll
    for (int c = 0; c < 2; ++c) {
        const int k0w = i * 16 + c * 8;
        unsigned ah[4];
        ldsm4(ah, qh + ar * STR68 + k0w + ac);
#pragma unroll
        for (int u = 0; u < 4; ++u) {
            unsigned bh[4];
            ldsm4(bh, kh + (16 * u + kr) * STR68 + k0w + kc);
            mma_f16(sc[2 * u],     ah, bh);
            mma_f16(sc[2 * u + 1], ah, bh + 2);
        }
    }
}

// ---------------- pass 1 ----------------
#define P1W_KH0 8704
#define P1W_KH1 13056
#define P1_SMEM_BYTES (17408 * 4)

__global__ __launch_bounds__(256, 3)
void attn_pass1()
{
    extern __shared__ unsigned usm[];
    unsigned* qh = usm;
    unsigned* khb[2] = { usm + P1W_KH0, usm + P1W_KH1 };

    const int tid = threadIdx.x;
    const int lane = tid & 31, w = tid >> 5;
    const int g = lane >> 2, tig = lane & 3;
    const int qt = gridDim.x - 1 - blockIdx.x;
    const int h = blockIdx.y, b = blockIdx.z;
    const int kvg = h >> 2;
    const int t0 = qt * 128;
    const int row0 = t0 + w * 16 + g;

    {
        size_t qoff = ((size_t)(b * Tt + t0) * Ee + h * 128) >> 1;
        copy_tile_async<128>(g_qh + qoff, Ee / 2, qh, tid);
        size_t koff = ((size_t)(b * Tt) * EKV + kvg * 128) >> 1;
        copy_tile_async<64>(g_kh + koff, EKV / 2, khb[0], tid);
        CP_COMMIT();
    }

    float rs[MM][2];
#pragma unroll
    for (int i = 0; i < MM; ++i) { rs[i][0] = 0.f; rs[i][1] = 0.f; }

    const int nst = 2 * qt + 2;
    for (int st = 0; st < nst; ++st) {
        int s0 = st * 64;
        if (st + 1 < nst) {
            size_t koff = ((size_t)(b * Tt + s0 + 64) * EKV + kvg * 128) >> 1;
            copy_tile_async<64>(g_kh + koff, EKV / 2, khb[(st + 1) & 1], tid);
            CP_COMMIT();
            CP_WAIT1();
        } else {
            CP_WAIT0();
        }
        __syncthreads();
        const unsigned* kh = khb[st & 1];

        if (s0 <= t0 + w * 16 + 15) {
            const bool full = (s0 + 63 <= t0 + w * 16);
            float scA[8][4], scB[8][4];
#pragma unroll
            for (int nt = 0; nt < 8; ++nt)
#pragma unroll
                for (int r = 0; r < 4; ++r) scA[nt][r] = 0.f;
            qk_member_f16_1t(qh, kh, w * 16, lane, 0, scA);
#pragma unroll
            for (int i = 0; i < MM; ++i) {
                float (*scc)[4] = (i & 1) ? scB : scA;
                float (*scn)[4] = (i & 1) ? scA : scB;
                if (i + 1 < MM) {
#pragma unroll
                    for (int nt = 0; nt < 8; ++nt)
#pragma unroll
                        for (int r = 0; r < 4; ++r) scn[nt][r] = 0.f;
                    qk_member_f16_1t(qh, kh, w * 16, lane, i + 1, scn);
                }
                if (full) {
#pragma unroll
                    for (int nt = 0; nt < 8; ++nt) {
                        rs[i][0] += exp2f(scc[nt][0]) + exp2f(scc[nt][1]);
                        rs[i][1] += exp2f(scc[nt][2]) + exp2f(scc[nt][3]);
                    }
                } else {
#pragma unroll
                    for (int nt = 0; nt < 8; ++nt) {
                        int col = s0 + nt * 8 + tig * 2;
                        if (col     <= row0)     rs[i][0] += exp2f(scc[nt][0]);
                        if (col + 1 <= row0)     rs[i][0] += exp2f(scc[nt][1]);
                        if (col     <= row0 + 8) rs[i][1] += exp2f(scc[nt][2]);
                        if (col + 1 <= row0 + 8) rs[i][1] += exp2f(scc[nt][3]);
                    }
                }
            }
        }
        __syncthreads();
    }

#pragma unroll
    for (int i = 0; i < MM; ++i) {
        rs[i][0] += __shfl_xor_sync(0xffffffffu, rs[i][0], 1);
        rs[i][0] += __shfl_xor_sync(0xffffffffu, rs[i][0], 2);
        rs[i][1] += __shfl_xor_sync(0xffffffffu, rs[i][1], 1);
        rs[i][1] += __shfl_xor_sync(0xffffffffu, rs[i][1], 2);
        if (tig == 0) {
            size_t base = (((size_t)b * Hh + h) * MM + i) * Tt;
            g_L[base + row0]     = rs[i][0];
            g_L[base + row0 + 8] = rs[i][1];
        }
    }
}

// ---------------- pass 2 ----------------
#define P2W_QL   8704
#define P2W_KH0  17408
#define P2W_KH1  21760
#define P2W_VH0  26112
#define P2W_VH1  30464
#define P2W_LINV 34816
#define P2W_GM   35328
#define P2_SMEM_BYTES (35456 * 4)

__device__ __forceinline__ void pack_pj(const float p[8][4], int j,
                                        unsigned ph[4], unsigned pl[4])
{
    ph[0] = pack_f16(p[2 * j][0], p[2 * j][1]);
    ph[1] = pack_f16(p[2 * j][2], p[2 * j][3]);
    ph[2] = pack_f16(p[2 * j + 1][0], p[2 * j + 1][1]);
    ph[3] = pack_f16(p[2 * j + 1][2], p[2 * j + 1][3]);
    float2 f0 = unpack_f16(ph[0]), f1 = unpack_f16(ph[1]);
    float2 f2 = unpack_f16(ph[2]), f3 = unpack_f16(ph[3]);
    pl[0] = pack_f16(p[2 * j][0] - f0.x, p[2 * j][1] - f0.y);
    pl[1] = pack_f16(p[2 * j][2] - f1.x, p[2 * j][3] - f1.y);
    pl[2] = pack_f16(p[2 * j + 1][0] - f2.x, p[2 * j + 1][1] - f2.y);
    pl[3] = pack_f16(p[2 * j + 1][2] - f3.x, p[2 * j + 1][3] - f3.y);
}

__global__ __launch_bounds__(256, 1)
void attn_pass2(const float* __restrict__ raw_w,
                const float* __restrict__ wscale,
                const float* __restrict__ gamma)
{
    extern __shared__ unsigned usm[];
    unsigned* qh = usm;
    unsigned* ql = usm + P2W_QL;
    unsigned* khb[2] = { usm + P2W_KH0, usm + P2W_KH1 };
    unsigned* vhb[2] = { usm + P2W_VH0, usm + P2W_VH1 };
    float* linv = (float*)(usm + P2W_LINV);
    float* gms  = (float*)(usm + P2W_GM);

    const int tid = threadIdx.x;
    const int lane = tid & 31, w = tid >> 5;
    const int g = lane >> 2, tig = lane & 3;
    const int qt = gridDim.x - 1 - blockIdx.x;
    const int h = blockIdx.y, b = blockIdx.z;
    const int kvg = h >> 2;
    const int t0 = qt * 128;
    const int row0 = t0 + w * 16 + g;

    {
        size_t qoff = ((size_t)(b * Tt + t0) * Ee + h * 128) >> 1;
        copy_tile_async<128>(g_qh + qoff, Ee / 2, qh, tid);
        copy_tile_async<128>(g_ql + qoff, Ee / 2, ql, tid);
        size_t koff = ((size_t)(b * Tt) * EKV + kvg * 128) >> 1;
        copy_tile_async<64>(g_kh + koff, EKV / 2, khb[0], tid);
        copy_tile_async<64>(g_vh + koff, EKV / 2, vhb[0], tid);
        CP_COMMIT();
    }
    if (tid < 128) {
        float ws = wscale[0];
#pragma unroll
        for (int i = 0; i < MM; ++i) {
            float wi = tanhf(raw_w[i]) * ws;
            float l = g_L[(((size_t)b * Hh + h) * MM + i) * Tt + t0 + tid];
            linv[i * 128 + tid] = wi / l;
        }
        gms[tid] = gamma[tid];
    }

    float o[16][4];
#pragma unroll
    for (int nt = 0; nt < 16; ++nt)
#pragma unroll
        for (int r = 0; r < 4; ++r) o[nt][r] = 0.f;

    const int nst = 2 * qt + 2;
    for (int st = 0; st < nst; ++st) {
        int s0 = st * 64;
        if (st + 1 < nst) {
            size_t koff = ((size_t)(b * Tt + s0 + 64) * EKV + kvg * 128) >> 1;
            copy_tile_async<64>(g_kh + koff, EKV / 2, khb[(st + 1) & 1], tid);
            copy_tile_async<64>(g_vh + koff, EKV / 2, vhb[(st + 1) & 1], tid);
            CP_COMMIT();
            CP_WAIT1();
        } else {
            CP_WAIT0();
        }
        __syncthreads();
        const unsigned* kh = khb[st & 1];
        const unsigned* vh = vhb[st & 1];

        const bool active = (s0 <= t0 + w * 16 + 15);
        const bool full   = (s0 + 63 <= t0 + w * 16);

        if (active) {
            float p[8][4];
#pragma unroll
            for (int nt = 0; nt < 8; ++nt)
#pragma unroll
                for (int r = 0; r < 4; ++r) p[nt][r] = 0.f;

            // software-pipelined member loop: QK mma of member i+1 issues
            // before member i's exp phase (tensor and MUFU overlap).
            float scA[8][4], scB[8][4];
#pragma unroll
            for (int nt = 0; nt < 8; ++nt)
#pragma unroll
                for (int r = 0; r < 4; ++r) scA[nt][r] = 0.f;
            qk_member_f16(qh, ql, kh, w * 16, lane, 0, scA);
#pragma unroll
            for (int i = 0; i < MM; ++i) {
                float (*scc)[4] = (i & 1) ? scB : scA;
                float (*scn)[4] = (i & 1) ? scA : scB;
                if (i + 1 < MM) {
#pragma unroll
                    for (int nt = 0; nt < 8; ++nt)
#pragma unroll
                        for (int r = 0; r < 4; ++r) scn[nt][r] = 0.f;
                    qk_member_f16(qh, ql, kh, w * 16, lane, i + 1, scn);
                }
                float l0 = linv[i * 128 + w * 16 + g];
                float l1 = linv[i * 128 + w * 16 + g + 8];
                if (full) {
#pragma unroll
                    for (int nt = 0; nt < 8; ++nt) {
                        p[nt][0] += l0 * exp2f(scc[nt][0]);
                        p[nt][1] += l0 * exp2f(scc[nt][1]);
                        p[nt][2] += l1 * exp2f(scc[nt][2]);
                        p[nt][3] += l1 * exp2f(scc[nt][3]);
                    }
                } else {
#pragma unroll
                    for (int nt = 0; nt < 8; ++nt) {
                        int col = s0 + nt * 8 + tig * 2;
                        if (col     <= row0)     p[nt][0] += l0 * exp2f(scc[nt][0]);
                        if (col + 1 <= row0)     p[nt][1] += l0 * exp2f(scc[nt][1]);
                        if (col     <= row0 + 8) p[nt][2] += l1 * exp2f(scc[nt][2]);
                        if (col + 1 <= row0 + 8) p[nt][3] += l1 * exp2f(scc[nt][3]);
                    }
                }
            }

            // PV: pack chunk j+1 before issuing chunk j's mma (CVT/tensor overlap)
            const int vrb = (lane & 7) + (((lane >> 3) & 1) << 3);
            const int vcb = (lane >> 4) << 2;
            unsigned phA[4], plA[4], phB[4], plB[4];
            pack_pj(p, 0, phA, plA);
#pragma unroll
            for (int j = 0; j < 4; ++j) {
                unsigned* phc = (j & 1) ? phB : phA;
                unsigned* plc = (j & 1) ? plB : plA;
                unsigned* phn = (j & 1) ? phA : phB;
                unsigned* pln = (j & 1) ? plA : plB;
                if (j + 1 < 4) pack_pj(p, j + 1, phn, pln);
                const int vr = 16 * j + vrb;
#pragma unroll
                for (int u = 0; u < 8; ++u) {
                    unsigned vb[4];
                    ldsm4t(vb, vh + vr * STR68 + 8 * u + vcb);
                    mma_f16(o[2 * u],     phc, vb);
                    mma_f16(o[2 * u + 1], phc, vb + 2);
                    mma_f16(o[2 * u],     plc, vb);
                    mma_f16(o[2 * u + 1], plc, vb + 2);
                }
            }
        }
        __syncthreads();
    }

    // fused RMSNorm (quad butterfly)
    float sq0 = 0.f, sq1 = 0.f;
#pragma unroll
    for (int nt = 0; nt < 16; ++nt) {
        sq0 += o[nt][0] * o[nt][0] + o[nt][1] * o[nt][1];
        sq1 += o[nt][2] * o[nt][2] + o[nt][3] * o[nt][3];
    }
    sq0 += __shfl_xor_sync(0xffffffffu, sq0, 1);
    sq0 += __shfl_xor_sync(0xffffffffu, sq0, 2);
    sq1 += __shfl_xor_sync(0xffffffffu, sq1, 1);
    sq1 += __shfl_xor_sync(0xffffffffu, sq1, 2);
    float rn0 = rsqrtf(sq0 * (1.f / 128.f) + 1e-5f);
    float rn1 = rsqrtf(sq1 * (1.f / 128.f) + 1e-5f);

#pragma unroll
    for (int nt = 0; nt < 16; ++nt) {
        float g0 = gms[nt * 8 + tig * 2];
        float g1 = gms[nt * 8 + tig * 2 + 1];
        size_t w0 = ((size_t)(b * Tt + row0) * Ee + h * 128 + nt * 8 + tig * 2) >> 1;
        size_t w1 = ((size_t)(b * Tt + row0 + 8) * Ee + h * 128 + nt * 8 + tig * 2) >> 1;
        g_nh[w0] = pack_f16(o[nt][0] * rn0 * g0, o[nt][1] * rn0 * g1);
        g_nh[w1] = pack_f16(o[nt][2] * rn1 * g0, o[nt][3] * rn1 * g1);
    }
}

// ============================================================
extern "C" void kernel_launch(void* const* d_in, const int* in_sizes, int n_in,
                              void* d_out, int out_size)
{
    const float* x      = (const float*)d_in[0];
    const float* cosp   = (const float*)d_in[1];
    const float* sinp   = (const float*)d_in[2];
    const float* q_w    = (const float*)d_in[3];
    const float* k_w    = (const float*)d_in[4];
    const float* v_w    = (const float*)d_in[5];
    const float* out_w  = (const float*)d_in[6];
    const float* raw_w  = (const float*)d_in[7];
    const float* wscale = (const float*)d_in[8];
    const float* gamma  = (const float*)d_in[9];

    unsigned *qhb, *qlb, *khb, *vhb, *nhb;
    unsigned *xh, *qwh, *kwh, *vwh, *owh;
    cudaGetSymbolAddress((void**)&qhb, g_qh);
    cudaGetSymbolAddress((void**)&qlb, g_ql);
    cudaGetSymbolAddress((void**)&khb, g_kh);
    cudaGetSymbolAddress((void**)&vhb, g_vh);
    cudaGetSymbolAddress((void**)&nhb, g_nh);
    cudaGetSymbolAddress((void**)&xh, g_xh);
    cudaGetSymbolAddress((void**)&qwh, g_qwh);
    cudaGetSymbolAddress((void**)&kwh, g_kwh);
    cudaGetSymbolAddress((void**)&vwh, g_vwh);
    cudaGetSymbolAddress((void**)&owh, g_owh);

    cudaFuncSetAttribute(gemm_f16_v4<0>, cudaFuncAttributeMaxDynamicSharedMemorySize, G4_SMEM_BYTES);
    cudaFuncSetAttribute(gemm_f16_v4<2>, cudaFuncAttributeMaxDynamicSharedMemorySize, G4_SMEM_BYTES);
    cudaFuncSetAttribute(gemm_f16_v4<4>, cudaFuncAttributeMaxDynamicSharedMemorySize, G4_SMEM_BYTES);
    cudaFuncSetAttribute(gemm_f16_v4<5>, cudaFuncAttributeMaxDynamicSharedMemorySize, G4_SMEM_BYTES);
    cudaFuncSetAttribute(attn_pass1, cudaFuncAttributeMaxDynamicSharedMemorySize, P1_SMEM_BYTES);
    cudaFuncSetAttribute(attn_pass2, cudaFuncAttributeMaxDynamicSharedMemorySize, P2_SMEM_BYTES);

    // pack operands to fp16
    cvt_f16<<<(BT * Ee) / 1024, 256>>>(x, xh);
    cvt_f16<<<(Ee * Ee) / 1024, 256>>>(q_w, qwh);
    cvt_f16<<<(EKV * Ee) / 1024, 256>>>(k_w, kwh);
    cvt_f16<<<(EKV * Ee) / 1024, 256>>>(v_w, vwh);
    cvt_f16<<<(Ee * Ee) / 1024, 256>>>(out_w, owh);

    // fp16 projections (q: rope + scale + hi/lo; k: rope; v: plain)
    gemm_f16_v4<2><<<dim3(Ee / 128, BT / 128), 256, G4_SMEM_BYTES>>>(xh, qwh, nullptr, qhb, qlb, Ee, Ee, cosp, sinp);
    gemm_f16_v4<5><<<dim3(EKV / 128, BT / 128), 256, G4_SMEM_BYTES>>>(xh, kwh, nullptr, khb, nullptr, EKV, Ee, cosp, sinp);
    gemm_f16_v4<4><<<dim3(EKV / 128, BT / 128), 256, G4_SMEM_BYTES>>>(xh, vwh, nullptr, vhb, nullptr, EKV, Ee, nullptr, nullptr);

    // attention (pass1: 1-term, 3 CTA/SM; pass2: 2-term, software-pipelined)
    dim3 agrid(Tt / 128, Hh, Bb);
    attn_pass1<<<agrid, 256, P1_SMEM_BYTES>>>();
    attn_pass2<<<agrid, 256, P2_SMEM_BYTES>>>(raw_w, wscale, gamma);

    // fp16 output projection (f32 out)
    gemm_f16_v4<0><<<dim3(Ee / 128, BT / 128), 256, G4_SMEM_BYTES>>>(nhb, owh, (float*)d_out, nullptr, nullptr, Ee, Ee, nullptr, nullptr);
}

// round 17
// speedup vs baseline: 1.0898x; 1.0898x over previous
#include <cuda_runtime.h>
#include <cuda_fp16.h>
#include <math.h>

// Problem constants
#define Bb 2
#define Tt 2048
#define Ee 2048
#define BT (Bb*Tt)          // 4096
#define Hh 16
#define HKV 4
#define MM 4
#define HD 32
#define EKV 512
#define HALF 16             // HD/2
// q is pre-scaled by SCALEF*log2(e) in the q-projection epilogue,
// so scores feed exp2f directly.
#define QSCALE 0.25503485202f

// -------- scratch buffers (no cudaMalloc allowed) --------
__device__ __align__(128) unsigned g_qh[(size_t)BT * Ee / 2];   // q rope fp16 hi (pre-scaled)
__device__ __align__(128) unsigned g_ql[(size_t)BT * Ee / 2];   // q rope fp16 lo
__device__ __align__(128) unsigned g_kh[(size_t)BT * EKV / 2];  // k rope fp16
__device__ __align__(128) unsigned g_vh[(size_t)BT * EKV / 2];  // v fp16
__device__ __align__(128) float    g_L [(size_t)Bb * Hh * MM * Tt];
__device__ __align__(128) unsigned g_nh[(size_t)BT * Ee / 2];   // combined+rmsnorm fp16
// fp16-packed GEMM operands
__device__ __align__(128) unsigned g_xh [(size_t)BT * Ee / 2];
__device__ __align__(128) unsigned g_qwh[(size_t)Ee * Ee / 2];
__device__ __align__(128) unsigned g_kwh[(size_t)EKV * Ee / 2];
__device__ __align__(128) unsigned g_vwh[(size_t)EKV * Ee / 2];
__device__ __align__(128) unsigned g_owh[(size_t)Ee * Ee / 2];

// ------------------------------------------------------------
// helpers
// ------------------------------------------------------------
__device__ __forceinline__ void mma_f16(float c[4], const unsigned a[4], const unsigned b[2])
{
    asm volatile(
        "mma.sync.aligned.m16n8k16.row.col.f32.f16.f16.f32 "
        "{%0,%1,%2,%3}, {%4,%5,%6,%7}, {%8,%9}, {%0,%1,%2,%3};\n"
        : "+f"(c[0]), "+f"(c[1]), "+f"(c[2]), "+f"(c[3])
        : "r"(a[0]), "r"(a[1]), "r"(a[2]), "r"(a[3]), "r"(b[0]), "r"(b[1]));
}
__device__ __forceinline__ void ldsm4(unsigned r[4], const unsigned* p)
{
    unsigned a = (unsigned)__cvta_generic_to_shared(p);
    asm volatile("ldmatrix.sync.aligned.m8n8.x4.shared.b16 {%0,%1,%2,%3}, [%4];"
        : "=r"(r[0]), "=r"(r[1]), "=r"(r[2]), "=r"(r[3]) : "r"(a));
}
__device__ __forceinline__ void ldsm4t(unsigned r[4], const unsigned* p)
{
    unsigned a = (unsigned)__cvta_generic_to_shared(p);
    asm volatile("ldmatrix.sync.aligned.m8n8.x4.trans.shared.b16 {%0,%1,%2,%3}, [%4];"
        : "=r"(r[0]), "=r"(r[1]), "=r"(r[2]), "=r"(r[3]) : "r"(a));
}
__device__ __forceinline__ unsigned pack_f16(float lo, float hi)
{
    unsigned d;
    asm("cvt.rn.f16x2.f32 %0, %1, %2;\n" : "=r"(d) : "f"(hi), "f"(lo));
    return d;
}
__device__ __forceinline__ float2 unpack_f16(unsigned u)
{
    __half2 h = *reinterpret_cast<__half2*>(&u);
    return __half22float2(h);   // x = lo, y = hi
}
__device__ __forceinline__ void split_pair_f16(float v0, float v1, unsigned& hi, unsigned& lo)
{
    hi = pack_f16(v0, v1);
    float2 hf = unpack_f16(hi);
    lo = pack_f16(v0 - hf.x, v1 - hf.y);
}

#define CP_COMMIT() asm volatile("cp.async.commit_group;\n")
#define CP_WAIT0()  asm volatile("cp.async.wait_group 0;\n")
#define CP_WAIT1()  asm volatile("cp.async.wait_group 1;\n")
__device__ __forceinline__ void cp16(unsigned dst, const unsigned* src)
{
    asm volatile("cp.async.cg.shared.global [%0], [%1], 16;\n" :: "r"(dst), "l"(src));
}

// ------------------------------------------------------------
// f32 -> packed fp16 convert
// ------------------------------------------------------------
__global__ __launch_bounds__(256)
void cvt_f16(const float* __restrict__ s, unsigned* __restrict__ d)
{
    size_t i = ((size_t)blockIdx.x * 256 + threadIdx.x) * 4;
    float4 v = *(const float4*)(s + i);
    *(uint2*)(d + (i >> 1)) = make_uint2(pack_f16(v.x, v.y), pack_f16(v.z, v.w));
}

// ============================================================
// fp16 tensor-core GEMM: C[m,n] = sum_k A[m,k]*W[n,k]
// MODE 0: f32 out. MODE 2: RoPE + QSCALE + fp16 hi/lo out.
// MODE 4: fp16 out. MODE 5: RoPE + fp16 out.
// ============================================================
#define G4STR 36
#define G4_STAGE (128 * G4STR)
#define G4_SMEM_BYTES (4 * G4_STAGE * 4)

__device__ __forceinline__ void g4_issue(
    const unsigned* __restrict__ A, const unsigned* __restrict__ W,
    int Kw, int m0, int n0, int kw0,
    unsigned* __restrict__ asb, unsigned* __restrict__ bsb, int tid)
{
#pragma unroll
    for (int i = 0; i < 4; ++i) {
        int idx = tid + i * 256;
        int row = idx >> 3;
        int ch  = idx & 7;
        unsigned sA = (unsigned)__cvta_generic_to_shared(asb + row * G4STR + ch * 4);
        cp16(sA, A + (size_t)(m0 + row) * Kw + kw0 + ch * 4);
        unsigned sB = (unsigned)__cvta_generic_to_shared(bsb + row * G4STR + ch * 4);
        cp16(sB, W + (size_t)(n0 + row) * Kw + kw0 + ch * 4);
    }
    CP_COMMIT();
}

template<int MODE>
__global__ __launch_bounds__(256, 2)
void gemm_f16_v4(const unsigned* __restrict__ A, const unsigned* __restrict__ W,
                 float* __restrict__ C, unsigned* __restrict__ Chi,
                 unsigned* __restrict__ Clo, int N, int K,
                 const float* __restrict__ cosp, const float* __restrict__ sinp)
{
    extern __shared__ unsigned g4sm[];
    unsigned* As0 = g4sm;
    unsigned* As1 = g4sm + G4_STAGE;
    unsigned* Bs0 = g4sm + 2 * G4_STAGE;
    unsigned* Bs1 = g4sm + 3 * G4_STAGE;

    const int tid  = threadIdx.x;
    const int lane = tid & 31;
    const int warp = tid >> 5;
    const int g    = lane >> 2;
    const int tig  = lane & 3;
    const int wm   = warp >> 1;
    const int wn   = warp & 1;
    const int m0 = blockIdx.y * 128;
    const int n0 = blockIdx.x * 128;
    const int Kw = K / 2;

    const int a_row = lane & 15;
    const int a_c   = (lane >> 4) << 2;
    const int b_row = (lane & 7) + ((lane >> 4) << 3);
    const int b_c   = ((lane >> 3) & 1) << 2;

    float c[2][8][4];
#pragma unroll
    for (int mt = 0; mt < 2; ++mt)
#pragma unroll
        for (int nt = 0; nt < 8; ++nt)
#pragma unroll
            for (int r = 0; r < 4; ++r) c[mt][nt][r] = 0.f;

    g4_issue(A, W, Kw, m0, n0, 0, As0, Bs0, tid);

    const int NT = K / 64;
    for (int kt = 0; kt < NT; ++kt) {
        if (kt + 1 < NT) {
            g4_issue(A, W, Kw, m0, n0, (kt + 1) * 32,
                     ((kt + 1) & 1) ? As1 : As0, ((kt + 1) & 1) ? Bs1 : Bs0, tid);
            CP_WAIT1();
        } else {
            CP_WAIT0();
        }
        __syncthreads();

        const unsigned* ab = ((kt & 1) ? As1 : As0) + (wm * 32) * G4STR;
        const unsigned* bb = ((kt & 1) ? Bs1 : Bs0) + (wn * 64) * G4STR;

#pragma unroll
        for (int kc = 0; kc < 4; ++kc) {
            const int k0w = kc * 8;
            unsigned a[2][4], b[8][2];
#pragma unroll
            for (int mt = 0; mt < 2; ++mt)
                ldsm4(a[mt], ab + (mt * 16 + a_row) * G4STR + k0w + a_c);
#pragma unroll
            for (int u = 0; u < 4; ++u) {
                unsigned r[4];
                ldsm4(r, bb + (u * 16 + b_row) * G4STR + k0w + b_c);
                b[2 * u][0]     = r[0];
                b[2 * u][1]     = r[1];
                b[2 * u + 1][0] = r[2];
                b[2 * u + 1][1] = r[3];
            }
#pragma unroll
            for (int mt = 0; mt < 2; ++mt)
#pragma unroll
                for (int nt = 0; nt < 8; ++nt)
                    mma_f16(c[mt][nt], a[mt], b[nt]);
        }
        __syncthreads();
    }

#pragma unroll
    for (int mt = 0; mt < 2; ++mt) {
        int mA = m0 + wm * 32 + mt * 16 + g;
        int mB = mA + 8;
#pragma unroll
        for (int nt = 0; nt < 8; ++nt) {
            int n = n0 + wn * 64 + nt * 8 + tig * 2;
            float v0 = c[mt][nt][0], v1 = c[mt][nt][1];
            float v2 = c[mt][nt][2], v3 = c[mt][nt][3];
            if (MODE == 2 || MODE == 5) {
                int p = (n & 31) >> 1;
                int tA = mA & (Tt - 1), tB = mB & (Tt - 1);
                float cA = cosp[tA * HALF + p], snA = sinp[tA * HALF + p];
                float cB = cosp[tB * HALF + p], snB = sinp[tB * HALF + p];
                float e = v0, o = v1;
                v0 = e * cA - o * snA; v1 = e * snA + o * cA;
                e = v2; o = v3;
                v2 = e * cB - o * snB; v3 = e * snB + o * cB;
            }
            if (MODE == 2) {
                v0 *= QSCALE; v1 *= QSCALE; v2 *= QSCALE; v3 *= QSCALE;
                unsigned hi, lo;
                split_pair_f16(v0, v1, hi, lo);
                size_t wA = ((size_t)mA * N + n) >> 1;
                Chi[wA] = hi; Clo[wA] = lo;
                split_pair_f16(v2, v3, hi, lo);
                size_t wB = ((size_t)mB * N + n) >> 1;
                Chi[wB] = hi; Clo[wB] = lo;
            } else if (MODE == 4 || MODE == 5) {
                Chi[((size_t)mA * N + n) >> 1] = pack_f16(v0, v1);
                Chi[((size_t)mB * N + n) >> 1] = pack_f16(v2, v3);
            } else {
                *(float2*)(C + (size_t)mA * N + n) = make_float2(v0, v1);
                *(float2*)(C + (size_t)mB * N + n) = make_float2(v2, v3);
            }
        }
    }
}

// ============================================================
// split-fp16 attention, 2-pass. Scores come out exp2-ready.
// pass1: 1-term QK -> denominators only, 3 CTA/SM.
// pass2: 2-term QK + 1-term PV (P fp16-rounded; error ~1.4e-4).
// ============================================================
#define STR68 68

template<int ROWS>
__device__ __forceinline__ void copy_tile_async(const unsigned* __restrict__ gsrc, int grs,
                                                unsigned* __restrict__ dst, int tid)
{
#pragma unroll
    for (int it = 0; it < ROWS / 16; ++it) {
        int idx = tid + it * 256;
        int row = idx >> 4;
        int c4  = (idx & 15) << 2;
        unsigned s = (unsigned)__cvta_generic_to_shared(dst + row * STR68 + c4);
        const unsigned* gp = gsrc + (size_t)row * grs + c4;
        asm volatile("cp.async.cg.shared.global [%0], [%1], 16;\n" :: "r"(s), "l"(gp));
    }
}

__device__ __forceinline__ void qk_member_f16(
    const unsigned* __restrict__ qh, const unsigned* __restrict__ ql,
    const unsigned* __restrict__ kh,
    int qrow0, int lane, int i, float sc[8][4])
{
    const int ar = qrow0 + (lane & 15);
    const int ac = (lane >> 4) << 2;
    const int kr = (lane & 7) + ((lane >> 4) << 3);
    const int kc = ((lane >> 3) & 1) << 2;
#pragma unroll
    for (int c = 0; c < 2; ++c) {
        const int k0w = i * 16 + c * 8;
        unsigned ah[4], al[4];
        ldsm4(ah, qh + ar * STR68 + k0w + ac);
        ldsm4(al, ql + ar * STR68 + k0w + ac);
#pragma unroll
        for (int u = 0; u < 4; ++u) {
            unsigned bh[4];
            ldsm4(bh, kh + (16 * u + kr) * STR68 + k0w + kc);
            mma_f16(sc[2 * u],     ah, bh);
            mma_f16(sc[2 * u + 1], ah, bh + 2);
            mma_f16(sc[2 * u],     al, bh);
            mma_f16(sc[2 * u + 1], al, bh + 2);
        }
    }
}

__device__ __forceinline__ void qk_member_f16_1t(
    const unsigned* __restrict__ qh, const unsigned* __restrict__ kh,
    int qrow0, int lane, int i, float sc[8][4])
{
    const int ar = qrow0 + (lane & 15);
    const int ac = (lane >> 4) << 2;
    const int kr = (lane & 7) + ((lane >> 4) << 3);
    const int kc = ((lane >> 3) & 1) << 2;
#pragma unroll
    for (int c = 0; c < 2; ++c) {
        const int k0w = i * 16 + c * 8;
        unsigned ah[4];
        ldsm4(ah, qh + ar * STR68 + k0w + ac);
#pragma unroll
        for (int u = 0; u < 4; ++u) {
            unsigned bh[4];
            ldsm4(bh, kh + (16 * u + kr) * STR68 + k0w + kc);
            mma_f16(sc[2 * u],     ah, bh);
            mma_f16(sc[2 * u + 1], ah, bh + 2);
        }
    }
}

// ---------------- pass 1 ----------------
#define P1W_KH0 8704
#define P1W_KH1 13056
#define P1_SMEM_BYTES (17408 * 4)

__global__ __launch_bounds__(256, 3)
void attn_pass1()
{
    extern __shared__ unsigned usm[];
    unsigned* qh = usm;
    unsigned* khb[2] = { usm + P1W_KH0, usm + P1W_KH1 };

    const int tid = threadIdx.x;
    const int lane = tid & 31, w = tid >> 5;
    const int g = lane >> 2, tig = lane & 3;
    const int qt = gridDim.x - 1 - blockIdx.x;
    const int h = blockIdx.y, b = blockIdx.z;
    const int kvg = h >> 2;
    const int t0 = qt * 128;
    const int row0 = t0 + w * 16 + g;

    {
        size_t qoff = ((size_t)(b * Tt + t0) * Ee + h * 128) >> 1;
        copy_tile_async<128>(g_qh + qoff, Ee / 2, qh, tid);
        size_t koff = ((size_t)(b * Tt) * EKV + kvg * 128) >> 1;
        copy_tile_async<64>(g_kh + koff, EKV / 2, khb[0], tid);
        CP_COMMIT();
    }

    float rs[MM][2];
#pragma unroll
    for (int i = 0; i < MM; ++i) { rs[i][0] = 0.f; rs[i][1] = 0.f; }

    const int nst = 2 * qt + 2;
    for (int st = 0; st < nst; ++st) {
        int s0 = st * 64;
        if (st + 1 < nst) {
            size_t koff = ((size_t)(b * Tt + s0 + 64) * EKV + kvg * 128) >> 1;
            copy_tile_async<64>(g_kh + koff, EKV / 2, khb[(st + 1) & 1], tid);
            CP_COMMIT();
            CP_WAIT1();
        } else {
            CP_WAIT0();
        }
        __syncthreads();
        const unsigned* kh = khb[st & 1];

        if (s0 <= t0 + w * 16 + 15) {
            const bool full = (s0 + 63 <= t0 + w * 16);
#pragma unroll
            for (int i = 0; i < MM; ++i) {
                float sc[8][4];
#pragma unroll
                for (int nt = 0; nt < 8; ++nt)
#pragma unroll
                    for (int r = 0; r < 4; ++r) sc[nt][r] = 0.f;
                qk_member_f16_1t(qh, kh, w * 16, lane, i, sc);
                if (full) {
#pragma unroll
                    for (int nt = 0; nt < 8; ++nt) {
                        rs[i][0] += exp2f(sc[nt][0]) + exp2f(sc[nt][1]);
                        rs[i][1] += exp2f(sc[nt][2]) + exp2f(sc[nt][3]);
                    }
                } else {
#pragma unroll
                    for (int nt = 0; nt < 8; ++nt) {
                        int col = s0 + nt * 8 + tig * 2;
                        if (col     <= row0)     rs[i][0] += exp2f(sc[nt][0]);
                        if (col + 1 <= row0)     rs[i][0] += exp2f(sc[nt][1]);
                        if (col     <= row0 + 8) rs[i][1] += exp2f(sc[nt][2]);
                        if (col + 1 <= row0 + 8) rs[i][1] += exp2f(sc[nt][3]);
                    }
                }
            }
        }
        __syncthreads();
    }

#pragma unroll
    for (int i = 0; i < MM; ++i) {
        rs[i][0] += __shfl_xor_sync(0xffffffffu, rs[i][0], 1);
        rs[i][0] += __shfl_xor_sync(0xffffffffu, rs[i][0], 2);
        rs[i][1] += __shfl_xor_sync(0xffffffffu, rs[i][1], 1);
        rs[i][1] += __shfl_xor_sync(0xffffffffu, rs[i][1], 2);
        if (tig == 0) {
            size_t base = (((size_t)b * Hh + h) * MM + i) * Tt;
            g_L[base + row0]     = rs[i][0];
            g_L[base + row0 + 8] = rs[i][1];
        }
    }
}

// ---------------- pass 2 ----------------
#define P2W_QL   8704
#define P2W_KH0  17408
#define P2W_KH1  21760
#define P2W_VH0  26112
#define P2W_VH1  30464
#define P2W_LINV 34816
#define P2W_GM   35328
#define P2_SMEM_BYTES (35456 * 4)

__global__ __launch_bounds__(256, 1)
void attn_pass2(const float* __restrict__ raw_w,
                const float* __restrict__ wscale,
                const float* __restrict__ gamma)
{
    extern __shared__ unsigned usm[];
    unsigned* qh = usm;
    unsigned* ql = usm + P2W_QL;
    unsigned* khb[2] = { usm + P2W_KH0, usm + P2W_KH1 };
    unsigned* vhb[2] = { usm + P2W_VH0, usm + P2W_VH1 };
    float* linv = (float*)(usm + P2W_LINV);
    float* gms  = (float*)(usm + P2W_GM);

    const int tid = threadIdx.x;
    const int lane = tid & 31, w = tid >> 5;
    const int g = lane >> 2, tig = lane & 3;
    const int qt = gridDim.x - 1 - blockIdx.x;
    const int h = blockIdx.y, b = blockIdx.z;
    const int kvg = h >> 2;
    const int t0 = qt * 128;
    const int row0 = t0 + w * 16 + g;

    {
        size_t qoff = ((size_t)(b * Tt + t0) * Ee + h * 128) >> 1;
        copy_tile_async<128>(g_qh + qoff, Ee / 2, qh, tid);
        copy_tile_async<128>(g_ql + qoff, Ee / 2, ql, tid);
        size_t koff = ((size_t)(b * Tt) * EKV + kvg * 128) >> 1;
        copy_tile_async<64>(g_kh + koff, EKV / 2, khb[0], tid);
        copy_tile_async<64>(g_vh + koff, EKV / 2, vhb[0], tid);
        CP_COMMIT();
    }
    if (tid < 128) {
        float ws = wscale[0];
#pragma unroll
        for (int i = 0; i < MM; ++i) {
            float wi = tanhf(raw_w[i]) * ws;
            float l = g_L[(((size_t)b * Hh + h) * MM + i) * Tt + t0 + tid];
            linv[i * 128 + tid] = wi / l;
        }
        gms[tid] = gamma[tid];
    }

    float o[16][4];
#pragma unroll
    for (int nt = 0; nt < 16; ++nt)
#pragma unroll
        for (int r = 0; r < 4; ++r) o[nt][r] = 0.f;

    const int nst = 2 * qt + 2;
    for (int st = 0; st < nst; ++st) {
        int s0 = st * 64;
        if (st + 1 < nst) {
            size_t koff = ((size_t)(b * Tt + s0 + 64) * EKV + kvg * 128) >> 1;
            copy_tile_async<64>(g_kh + koff, EKV / 2, khb[(st + 1) & 1], tid);
            copy_tile_async<64>(g_vh + koff, EKV / 2, vhb[(st + 1) & 1], tid);
            CP_COMMIT();
            CP_WAIT1();
        } else {
            CP_WAIT0();
        }
        __syncthreads();
        const unsigned* kh = khb[st & 1];
        const unsigned* vh = vhb[st & 1];

        const bool active = (s0 <= t0 + w * 16 + 15);
        const bool full   = (s0 + 63 <= t0 + w * 16);

        if (active) {
            float p[8][4];
#pragma unroll
            for (int nt = 0; nt < 8; ++nt)
#pragma unroll
                for (int r = 0; r < 4; ++r) p[nt][r] = 0.f;
#pragma unroll
            for (int i = 0; i < MM; ++i) {
                float sc[8][4];
#pragma unroll
                for (int nt = 0; nt < 8; ++nt)
#pragma unroll
                    for (int r = 0; r < 4; ++r) sc[nt][r] = 0.f;
                qk_member_f16(qh, ql, kh, w * 16, lane, i, sc);
                float l0 = linv[i * 128 + w * 16 + g];
                float l1 = linv[i * 128 + w * 16 + g + 8];
                if (full) {
#pragma unroll
                    for (int nt = 0; nt < 8; ++nt) {
                        p[nt][0] += l0 * exp2f(sc[nt][0]);
                        p[nt][1] += l0 * exp2f(sc[nt][1]);
                        p[nt][2] += l1 * exp2f(sc[nt][2]);
                        p[nt][3] += l1 * exp2f(sc[nt][3]);
                    }
                } else {
#pragma unroll
                    for (int nt = 0; nt < 8; ++nt) {
                        int col = s0 + nt * 8 + tig * 2;
                        if (col     <= row0)     p[nt][0] += l0 * exp2f(sc[nt][0]);
                        if (col + 1 <= row0)     p[nt][1] += l0 * exp2f(sc[nt][1]);
                        if (col     <= row0 + 8) p[nt][2] += l1 * exp2f(sc[nt][2]);
                        if (col + 1 <= row0 + 8) p[nt][3] += l1 * exp2f(sc[nt][3]);
                    }
                }
            }

            // PV: 1-term (P fp16-rounded), ldmatrix.trans V fragments
            const int vrb = (lane & 7) + (((lane >> 3) & 1) << 3);
            const int vcb = (lane >> 4) << 2;
#pragma unroll
            for (int j = 0; j < 4; ++j) {
                unsigned ph[4];
                ph[0] = pack_f16(p[2 * j][0], p[2 * j][1]);
                ph[1] = pack_f16(p[2 * j][2], p[2 * j][3]);
                ph[2] = pack_f16(p[2 * j + 1][0], p[2 * j + 1][1]);
                ph[3] = pack_f16(p[2 * j + 1][2], p[2 * j + 1][3]);
                const int vr = 16 * j + vrb;
#pragma unroll
                for (int u = 0; u < 8; ++u) {
                    unsigned vb[4];
                    ldsm4t(vb, vh + vr * STR68 + 8 * u + vcb);
                    mma_f16(o[2 * u],     ph, vb);
                    mma_f16(o[2 * u + 1], ph, vb + 2);
                }
            }
        }
        __syncthreads();
    }

    // fused RMSNorm (quad butterfly)
    float sq0 = 0.f, sq1 = 0.f;
#pragma unroll
    for (int nt = 0; nt < 16; ++nt) {
        sq0 += o[nt][0] * o[nt][0] + o[nt][1] * o[nt][1];
        sq1 += o[nt][2] * o[nt][2] + o[nt][3] * o[nt][3];
    }
    sq0 += __shfl_xor_sync(0xffffffffu, sq0, 1);
    sq0 += __shfl_xor_sync(0xffffffffu, sq0, 2);
    sq1 += __shfl_xor_sync(0xffffffffu, sq1, 1);
    sq1 += __shfl_xor_sync(0xffffffffu, sq1, 2);
    float rn0 = rsqrtf(sq0 * (1.f / 128.f) + 1e-5f);
    float rn1 = rsqrtf(sq1 * (1.f / 128.f) + 1e-5f);

#pragma unroll
    for (int nt = 0; nt < 16; ++nt) {
        float g0 = gms[nt * 8 + tig * 2];
        float g1 = gms[nt * 8 + tig * 2 + 1];
        size_t w0 = ((size_t)(b * Tt + row0) * Ee + h * 128 + nt * 8 + tig * 2) >> 1;
        size_t w1 = ((size_t)(b * Tt + row0 + 8) * Ee + h * 128 + nt * 8 + tig * 2) >> 1;
        g_nh[w0] = pack_f16(o[nt][0] * rn0 * g0, o[nt][1] * rn0 * g1);
        g_nh[w1] = pack_f16(o[nt][2] * rn1 * g0, o[nt][3] * rn1 * g1);
    }
}

// ============================================================
extern "C" void kernel_launch(void* const* d_in, const int* in_sizes, int n_in,
                              void* d_out, int out_size)
{
    const float* x      = (const float*)d_in[0];
    const float* cosp   = (const float*)d_in[1];
    const float* sinp   = (const float*)d_in[2];
    const float* q_w    = (const float*)d_in[3];
    const float* k_w    = (const float*)d_in[4];
    const float* v_w    = (const float*)d_in[5];
    const float* out_w  = (const float*)d_in[6];
    const float* raw_w  = (const float*)d_in[7];
    const float* wscale = (const float*)d_in[8];
    const float* gamma  = (const float*)d_in[9];

    unsigned *qhb, *qlb, *khb, *vhb, *nhb;
    unsigned *xh, *qwh, *kwh, *vwh, *owh;
    cudaGetSymbolAddress((void**)&qhb, g_qh);
    cudaGetSymbolAddress((void**)&qlb, g_ql);
    cudaGetSymbolAddress((void**)&khb, g_kh);
    cudaGetSymbolAddress((void**)&vhb, g_vh);
    cudaGetSymbolAddress((void**)&nhb, g_nh);
    cudaGetSymbolAddress((void**)&xh, g_xh);
    cudaGetSymbolAddress((void**)&qwh, g_qwh);
    cudaGetSymbolAddress((void**)&kwh, g_kwh);
    cudaGetSymbolAddress((void**)&vwh, g_vwh);
    cudaGetSymbolAddress((void**)&owh, g_owh);

    cudaFuncSetAttribute(gemm_f16_v4<0>, cudaFuncAttributeMaxDynamicSharedMemorySize, G4_SMEM_BYTES);
    cudaFuncSetAttribute(gemm_f16_v4<2>, cudaFuncAttributeMaxDynamicSharedMemorySize, G4_SMEM_BYTES);
    cudaFuncSetAttribute(gemm_f16_v4<4>, cudaFuncAttributeMaxDynamicSharedMemorySize, G4_SMEM_BYTES);
    cudaFuncSetAttribute(gemm_f16_v4<5>, cudaFuncAttributeMaxDynamicSharedMemorySize, G4_SMEM_BYTES);
    cudaFuncSetAttribute(attn_pass1, cudaFuncAttributeMaxDynamicSharedMemorySize, P1_SMEM_BYTES);
    cudaFuncSetAttribute(attn_pass2, cudaFuncAttributeMaxDynamicSharedMemorySize, P2_SMEM_BYTES);

    // pack operands to fp16
    cvt_f16<<<(BT * Ee) / 1024, 256>>>(x, xh);
    cvt_f16<<<(Ee * Ee) / 1024, 256>>>(q_w, qwh);
    cvt_f16<<<(EKV * Ee) / 1024, 256>>>(k_w, kwh);
    cvt_f16<<<(EKV * Ee) / 1024, 256>>>(v_w, vwh);
    cvt_f16<<<(Ee * Ee) / 1024, 256>>>(out_w, owh);

    // fp16 projections (q: rope + scale + hi/lo; k: rope; v: plain)
    gemm_f16_v4<2><<<dim3(Ee / 128, BT / 128), 256, G4_SMEM_BYTES>>>(xh, qwh, nullptr, qhb, qlb, Ee, Ee, cosp, sinp);
    gemm_f16_v4<5><<<dim3(EKV / 128, BT / 128), 256, G4_SMEM_BYTES>>>(xh, kwh, nullptr, khb, nullptr, EKV, Ee, cosp, sinp);
    gemm_f16_v4<4><<<dim3(EKV / 128, BT / 128), 256, G4_SMEM_BYTES>>>(xh, vwh, nullptr, vhb, nullptr, EKV, Ee, nullptr, nullptr);

    // attention (pass1: 1-term QK, 3 CTA/SM; pass2: 2-term QK + 1-term PV)
    dim3 agrid(Tt / 128, Hh, Bb);
    attn_pass1<<<agrid, 256, P1_SMEM_BYTES>>>();
    attn_pass2<<<agrid, 256, P2_SMEM_BYTES>>>(raw_w, wscale, gamma);

    // fp16 output projection (f32 out)
    gemm_f16_v4<0><<<dim3(Ee / 128, BT / 128), 256, G4_SMEM_BYTES>>>(nhb, owh, (float*)d_out, nullptr, nullptr, Ee, Ee, nullptr, nullptr);
}